// round 8
// baseline (speedup 1.0000x reference)
#include <cuda_runtime.h>
#include <cuda_bf16.h>
#include <stdint.h>

// ============================================================================
// Complex MHA on tensor cores (mma.sync m16n8k16 bf16, fp32 accum).
// All fp32 operands split x = hi(bf16) + lo(bf16); products use 3 passes
// (hh + hl + lh)  ->  ~2^-17 relative product error.
// R7: cp.async double-buffered pipelines in cgemm + attn; merged conv.
// ============================================================================

typedef __nv_bfloat16  bf;
typedef __nv_bfloat162 bf2;
typedef uint32_t u32;

#define NTOK 2048
#define HH   8
#define NIN  (4096 * 512)
#define NW   (512 * 512)

// ------------------------------ scratch -------------------------------------
__device__ __align__(16) bf g_in [12][NIN];            // inputs  r/i x hi/lo
__device__ __align__(16) bf g_w  [16][NW];             // weights x hi/lo
__device__ __align__(16) bf g_qkv[12][16 * 2048 * 64]; // q,k,v (r/i x h/l)
__device__ __align__(16) bf g_ao [4][4096 * 512];      // attn out r/i x hi/lo

// ------------------------------ helpers -------------------------------------
__device__ __forceinline__ void ldsm4(u32* r, const bf* p) {
    u32 a = (u32)__cvta_generic_to_shared(p);
    asm volatile("ldmatrix.sync.aligned.m8n8.x4.shared.b16 {%0,%1,%2,%3},[%4];"
                 : "=r"(r[0]), "=r"(r[1]), "=r"(r[2]), "=r"(r[3]) : "r"(a));
}
__device__ __forceinline__ void ldsm4t(u32* r, const bf* p) {
    u32 a = (u32)__cvta_generic_to_shared(p);
    asm volatile("ldmatrix.sync.aligned.m8n8.x4.trans.shared.b16 {%0,%1,%2,%3},[%4];"
                 : "=r"(r[0]), "=r"(r[1]), "=r"(r[2]), "=r"(r[3]) : "r"(a));
}
__device__ __forceinline__ void mma_(float* c, const u32* a, u32 b0, u32 b1) {
    asm volatile(
        "mma.sync.aligned.m16n8k16.row.col.f32.bf16.bf16.f32 "
        "{%0,%1,%2,%3},{%4,%5,%6,%7},{%8,%9},{%0,%1,%2,%3};"
        : "+f"(c[0]), "+f"(c[1]), "+f"(c[2]), "+f"(c[3])
        : "r"(a[0]), "r"(a[1]), "r"(a[2]), "r"(a[3]), "r"(b0), "r"(b1));
}
__device__ __forceinline__ void cpa(bf* dst, const bf* src) {
    u32 a = (u32)__cvta_generic_to_shared(dst);
    asm volatile("cp.async.cg.shared.global [%0],[%1],16;" :: "r"(a), "l"(src));
}
#define CP_COMMIT asm volatile("cp.async.commit_group;")
#define CP_WAIT1  asm volatile("cp.async.wait_group 1;")
#define CP_WAIT0  asm volatile("cp.async.wait_group 0;")

// non-trans ldsm pointer: rows = (lane&15), col block = (lane>>4)*8
__device__ __forceinline__ const bf* aptr(const bf* b_, int r0, int c0, int st, int ln) {
    return b_ + (r0 + (ln & 15)) * st + c0 + ((ln >> 4) << 3);
}
// trans ldsm pointer (for B from row-major (k,n)): k = (ln&7)+((ln>>3)&1)*8
__device__ __forceinline__ const bf* tptr(const bf* b_, int r0, int c0, int st, int ln) {
    return b_ + (r0 + (ln & 7) + ((ln >> 3) & 1) * 8) * st + c0 + ((ln >> 4) & 1) * 8;
}
__device__ __forceinline__ void split2(float x0, float x1, u32& hi, u32& lo) {
    bf h0 = __float2bfloat16(x0), h1 = __float2bfloat16(x1);
    bf l0 = __float2bfloat16(x0 - __bfloat162float(h0));
    bf l1 = __float2bfloat16(x1 - __bfloat162float(h1));
    bf2 h; h.x = h0; h.y = h1; bf2 l; l.x = l0; l.y = l1;
    hi = *(u32*)&h; lo = *(u32*)&l;
}

// ------------------- fp32 -> bf16 hi/lo split (merged) ----------------------
__global__ void conv_in(const float* s0, const float* s1, const float* s2,
                        const float* s3, const float* s4, const float* s5,
                        bf* inB) {
    const int t = blockIdx.y;
    const float* s;
    switch (t) {
        case 0: s = s0; break; case 1: s = s1; break; case 2: s = s2; break;
        case 3: s = s3; break; case 4: s = s4; break; default: s = s5; break;
    }
    bf* hi = inB + (size_t)(2 * t) * NIN;
    bf* lo = hi + NIN;
    int i = (blockIdx.x * 256 + threadIdx.x) * 4;
    float4 v = *(const float4*)(s + i);
    u32 h0, l0, h1, l1;
    split2(v.x, v.y, h0, l0);
    split2(v.z, v.w, h1, l1);
    *(u32*)(hi + i) = h0; *(u32*)(hi + i + 2) = h1;
    *(u32*)(lo + i) = l0; *(u32*)(lo + i + 2) = l1;
}

__global__ void conv_w(const float* s0, const float* s1, const float* s2,
                       const float* s3, const float* s4, const float* s5,
                       const float* s6, const float* s7, bf* wB) {
    const int t = blockIdx.y;
    const float* s;
    switch (t) {
        case 0: s = s0; break; case 1: s = s1; break; case 2: s = s2; break;
        case 3: s = s3; break; case 4: s = s4; break; case 5: s = s5; break;
        case 6: s = s6; break; default: s = s7; break;
    }
    const float sc = (t < 2) ? 0.125f : 1.0f;   // fold 1/sqrt(64) into wq
    bf* hi = wB + (size_t)(2 * t) * NW;
    bf* lo = hi + NW;
    int i = (blockIdx.x * 256 + threadIdx.x) * 4;
    float4 v = *(const float4*)(s + i);
    v.x *= sc; v.y *= sc; v.z *= sc; v.w *= sc;
    u32 h0, l0, h1, l1;
    split2(v.x, v.y, h0, l0);
    split2(v.z, v.w, h1, l1);
    *(u32*)(hi + i) = h0; *(u32*)(hi + i + 2) = h1;
    *(u32*)(lo + i) = l0; *(u32*)(lo + i + 2) = l1;
}

// ---------------------------------------------------------------------------
// Complex NT GEMM (M=4096, N=512, K=512), hi/lo 3-pass bf16 mma.
// Block tile 128x64 (8 warps 4x2, warp 32x32), cp.async 2-stage pipeline.
// ---------------------------------------------------------------------------
#define ASZ (128 * 40)
#define BSZ (64 * 40)
#define STG (4 * ASZ + 4 * BSZ)
#define GEMM_SMEM (2 * STG * 2)

template<int MODE>
__global__ void __launch_bounds__(256) cgemm(
    const bf* __restrict__ A0, const bf* __restrict__ A1,
    const bf* __restrict__ A2, const bf* __restrict__ A3,
    const bf* __restrict__ B0, const bf* __restrict__ B1,
    const bf* __restrict__ B2, const bf* __restrict__ B3,
    bf* __restrict__ C0, bf* __restrict__ C1,
    bf* __restrict__ C2, bf* __restrict__ C3, float* __restrict__ Co)
{
    extern __shared__ bf sm[];
    const int tid = threadIdx.x, lane = tid & 31, wid = tid >> 5;
    const int wm = wid >> 1, wn = wid & 1;
    const int mBase = blockIdx.y * 128, nBase = blockIdx.x * 64;

    const bf* Ap[4] = {A0, A1, A2, A3};
    const bf* Bp[4] = {B0, B1, B2, B3};

    float cre[2][4][4], cim[2][4][4];
#pragma unroll
    for (int a = 0; a < 2; a++)
#pragma unroll
        for (int b = 0; b < 4; b++)
#pragma unroll
            for (int c = 0; c < 4; c++) { cre[a][b][c] = 0.f; cim[a][b][c] = 0.f; }

    // stage issue: A 4x[128x32], B 4x[64x32] via cp.async
    auto issue = [&](int kc, int d) {
        bf* sA = sm + d * STG;
        bf* sB = sA + 4 * ASZ;
#pragma unroll
        for (int t = 0; t < 4; t++) {
#pragma unroll
            for (int i = 0; i < 2; i++) {
                int idx = i * 256 + tid, row = idx >> 2, col = (idx & 3) * 8;
                cpa(sA + t * ASZ + row * 40 + col,
                    Ap[t] + (size_t)(mBase + row) * 512 + kc * 32 + col);
            }
            int row = tid >> 2, col = (tid & 3) * 8;
            cpa(sB + t * BSZ + row * 40 + col,
                Bp[t] + (size_t)(nBase + row) * 512 + kc * 32 + col);
        }
    };

    issue(0, 0); CP_COMMIT;

    for (int kc = 0; kc < 16; kc++) {
        if (kc < 15) { issue(kc + 1, (kc + 1) & 1); CP_COMMIT; CP_WAIT1; }
        else         { CP_WAIT0; }
        __syncthreads();

        bf* sA = sm + (kc & 1) * STG;
        bf* sB = sA + 4 * ASZ;

#pragma unroll
        for (int ks = 0; ks < 2; ks++) {
            u32 af[4][2][4];
#pragma unroll
            for (int t = 0; t < 4; t++)
#pragma unroll
                for (int mt = 0; mt < 2; mt++)
                    ldsm4(af[t][mt], aptr(sA + t * ASZ, wm * 32 + mt * 16, ks * 16, 40, lane));
            u32 bg[4][8];
#pragma unroll
            for (int t = 0; t < 4; t++) {
                ldsm4(bg[t],     aptr(sB + t * BSZ, wn * 32,      ks * 16, 40, lane));
                ldsm4(bg[t] + 4, aptr(sB + t * BSZ, wn * 32 + 16, ks * 16, 40, lane));
            }
#pragma unroll
            for (int mt = 0; mt < 2; mt++) {
                u32 n2[4], n3[4];   // negated Ai hi/lo
#pragma unroll
                for (int r = 0; r < 4; r++) {
                    n2[r] = af[2][mt][r] ^ 0x80008000u;
                    n3[r] = af[3][mt][r] ^ 0x80008000u;
                }
#pragma unroll
                for (int nt = 0; nt < 4; nt++) {
                    int i0 = (nt >> 1) * 4 + (nt & 1), i1 = i0 + 2;
                    float* cr = cre[mt][nt]; float* ci = cim[mt][nt];
                    mma_(cr, af[0][mt], bg[0][i0], bg[0][i1]);
                    mma_(cr, af[0][mt], bg[1][i0], bg[1][i1]);
                    mma_(cr, af[1][mt], bg[0][i0], bg[0][i1]);
                    mma_(cr, n2,        bg[2][i0], bg[2][i1]);
                    mma_(cr, n2,        bg[3][i0], bg[3][i1]);
                    mma_(cr, n3,        bg[2][i0], bg[2][i1]);
                    mma_(ci, af[0][mt], bg[2][i0], bg[2][i1]);
                    mma_(ci, af[0][mt], bg[3][i0], bg[3][i1]);
                    mma_(ci, af[1][mt], bg[2][i0], bg[2][i1]);
                    mma_(ci, af[2][mt], bg[0][i0], bg[0][i1]);
                    mma_(ci, af[2][mt], bg[1][i0], bg[1][i1]);
                    mma_(ci, af[3][mt], bg[0][i0], bg[0][i1]);
                }
            }
        }
        __syncthreads();
    }

    const int g = lane >> 2, t2 = (lane & 3) * 2;
#pragma unroll
    for (int mt = 0; mt < 2; mt++)
#pragma unroll
        for (int nt = 0; nt < 4; nt++) {
            int c0 = wn * 32 + nt * 8 + t2;
#pragma unroll
            for (int hf = 0; hf < 2; hf++) {
                int m = mBase + wm * 32 + mt * 16 + g + hf * 8;
                float yr0 = cre[mt][nt][hf * 2], yr1 = cre[mt][nt][hf * 2 + 1];
                float yi0 = cim[mt][nt][hf * 2], yi1 = cim[mt][nt][hf * 2 + 1];
                if (MODE == 0) {
                    int b = m >> 11, ntok = m & 2047, h = blockIdx.x;
                    size_t base = ((size_t)((b * HH + h) * NTOK + ntok)) * 64 + c0;
                    u32 rh, rl, ih, il;
                    split2(yr0, yr1, rh, rl);
                    split2(yi0, yi1, ih, il);
                    *(u32*)(C0 + base) = rh; *(u32*)(C1 + base) = rl;
                    *(u32*)(C2 + base) = ih; *(u32*)(C3 + base) = il;
                } else {
                    size_t base = ((size_t)m * 512 + nBase + c0) * 2;
                    *(float4*)(Co + base) = make_float4(yr0, yi0, yr1, yi1);
                }
            }
        }
}

// ---------------------------------------------------------------------------
// Fused complex attention, cp.async 2-stage K/V pipeline.
// Grid (16 q-blocks, 16 bh). 8 warps; warp = 16 q rows x full 64-k tile.
// ---------------------------------------------------------------------------
#define QS (128 * 72)
#define KS (64 * 72)
#define KVSTG (8 * KS)
#define ATTN_SMEM ((4 * QS + 2 * KVSTG) * 2)

__global__ void __launch_bounds__(256) attn(
    const bf* __restrict__ q0p, const bf* __restrict__ q1p,
    const bf* __restrict__ q2p, const bf* __restrict__ q3p,
    const bf* __restrict__ k0p, const bf* __restrict__ k1p,
    const bf* __restrict__ k2p, const bf* __restrict__ k3p,
    const bf* __restrict__ v0p, const bf* __restrict__ v1p,
    const bf* __restrict__ v2p, const bf* __restrict__ v3p,
    bf* __restrict__ aorh, bf* __restrict__ aorl,
    bf* __restrict__ aoih, bf* __restrict__ aoil)
{
    extern __shared__ bf sm[];
    bf* sQ = sm;

    const int tid = threadIdx.x, lane = tid & 31, wid = tid >> 5;
    const int bh = blockIdx.y, q0 = blockIdx.x * 128;
    const bf* qp[4] = {q0p, q1p, q2p, q3p};
    const bf* kp[4] = {k0p, k1p, k2p, k3p};
    const bf* vp[4] = {v0p, v1p, v2p, v3p};

    auto issue_kv = [&](int kt, int d) {
        bf* sK = sm + 4 * QS + d * KVSTG;
        bf* sV = sK + 4 * KS;
#pragma unroll
        for (int t = 0; t < 4; t++)
#pragma unroll
            for (int i = 0; i < 2; i++) {
                int idx = i * 256 + tid, row = idx >> 3, col = (idx & 7) * 8;
                size_t go = ((size_t)(bh * NTOK + kt * 64 + row)) * 64 + col;
                cpa(sK + t * KS + row * 72 + col, kp[t] + go);
                cpa(sV + t * KS + row * 72 + col, vp[t] + go);
            }
    };

    issue_kv(0, 0); CP_COMMIT;

    // load Q tile once (plain stores; visible after first barrier)
#pragma unroll
    for (int t = 0; t < 4; t++)
#pragma unroll
        for (int i = 0; i < 4; i++) {
            int idx = i * 256 + tid, row = idx >> 3, col = (idx & 7) * 8;
            *(float4*)(sQ + t * QS + row * 72 + col) =
                *(const float4*)(qp[t] + ((size_t)(bh * NTOK + q0 + row)) * 64 + col);
        }

    float o_r[8][4], o_i[8][4];
#pragma unroll
    for (int a = 0; a < 8; a++)
#pragma unroll
        for (int b = 0; b < 4; b++) { o_r[a][b] = 0.f; o_i[a][b] = 0.f; }
    float ls0 = 0.f, ls1 = 0.f;

    for (int kt = 0; kt < 32; kt++) {
        if (kt < 31) { issue_kv(kt + 1, (kt + 1) & 1); CP_COMMIT; CP_WAIT1; }
        else         { CP_WAIT0; }
        __syncthreads();

        bf* sK = sm + 4 * QS + (kt & 1) * KVSTG;
        bf* sV = sK + 4 * KS;

        // ---- scores: S = Q conj(K)^T (hi/lo 3-pass) ----
        float sre[8][4], sim[8][4];
#pragma unroll
        for (int a = 0; a < 8; a++)
#pragma unroll
            for (int b = 0; b < 4; b++) { sre[a][b] = 0.f; sim[a][b] = 0.f; }

#pragma unroll
        for (int dc = 0; dc < 4; dc++) {
            u32 qf[4][4];
#pragma unroll
            for (int t = 0; t < 4; t++)
                ldsm4(qf[t], aptr(sQ + t * QS, wid * 16, dc * 16, 72, lane));
            u32 n0[4], n1[4];
#pragma unroll
            for (int r = 0; r < 4; r++) {
                n0[r] = qf[0][r] ^ 0x80008000u;
                n1[r] = qf[1][r] ^ 0x80008000u;
            }
#pragma unroll
            for (int nh = 0; nh < 2; nh++) {
                u32 kf[4][8];
#pragma unroll
                for (int t = 0; t < 4; t++) {
                    ldsm4(kf[t],     aptr(sK + t * KS, nh * 32,      dc * 16, 72, lane));
                    ldsm4(kf[t] + 4, aptr(sK + t * KS, nh * 32 + 16, dc * 16, 72, lane));
                }
#pragma unroll
                for (int n4 = 0; n4 < 4; n4++) {
                    int nt = nh * 4 + n4;
                    int i0 = (n4 >> 1) * 4 + (n4 & 1), i1 = i0 + 2;
                    float* cr = sre[nt]; float* ci = sim[nt];
                    mma_(cr, qf[0], kf[0][i0], kf[0][i1]);
                    mma_(cr, qf[0], kf[1][i0], kf[1][i1]);
                    mma_(cr, qf[1], kf[0][i0], kf[0][i1]);
                    mma_(cr, qf[2], kf[2][i0], kf[2][i1]);
                    mma_(cr, qf[2], kf[3][i0], kf[3][i1]);
                    mma_(cr, qf[3], kf[2][i0], kf[2][i1]);
                    mma_(ci, qf[2], kf[0][i0], kf[0][i1]);
                    mma_(ci, qf[2], kf[1][i0], kf[1][i1]);
                    mma_(ci, qf[3], kf[0][i0], kf[0][i1]);
                    mma_(ci, n0,    kf[2][i0], kf[2][i1]);
                    mma_(ci, n0,    kf[3][i0], kf[3][i1]);
                    mma_(ci, n1,    kf[2][i0], kf[2][i1]);
                }
            }
        }

        // ---- p = exp(|s|), register repack S-accum -> P A-frags ----
        u32 ph[4][4], pl[4][4];
#pragma unroll
        for (int kc = 0; kc < 4; kc++) {
            float pv[2][4];
#pragma unroll
            for (int h2 = 0; h2 < 2; h2++) {
                int nt = kc * 2 + h2;
#pragma unroll
                for (int e = 0; e < 4; e++) {
                    float u = sre[nt][e] * sre[nt][e] + sim[nt][e] * sim[nt][e];
                    pv[h2][e] = __expf(__fsqrt_rn(u));
                }
            }
            ls0 += pv[0][0] + pv[0][1] + pv[1][0] + pv[1][1];
            ls1 += pv[0][2] + pv[0][3] + pv[1][2] + pv[1][3];
            split2(pv[0][0], pv[0][1], ph[kc][0], pl[kc][0]);
            split2(pv[0][2], pv[0][3], ph[kc][1], pl[kc][1]);
            split2(pv[1][0], pv[1][1], ph[kc][2], pl[kc][2]);
            split2(pv[1][2], pv[1][3], ph[kc][3], pl[kc][3]);
        }

        // ---- O += P V (hi/lo 3-pass), V via trans ldmatrix ----
#pragma unroll
        for (int kc = 0; kc < 4; kc++)
#pragma unroll
            for (int dh = 0; dh < 2; dh++) {
                u32 vf[4][8];
#pragma unroll
                for (int t = 0; t < 4; t++) {
                    ldsm4t(vf[t],     tptr(sV + t * KS, kc * 16, dh * 32,      72, lane));
                    ldsm4t(vf[t] + 4, tptr(sV + t * KS, kc * 16, dh * 32 + 16, 72, lane));
                }
#pragma unroll
                for (int dt = 0; dt < 4; dt++) {
                    int od = dh * 4 + dt, j0 = dt * 2, j1 = dt * 2 + 1;
                    mma_(o_r[od], ph[kc], vf[0][j0], vf[0][j1]);
                    mma_(o_r[od], ph[kc], vf[1][j0], vf[1][j1]);
                    mma_(o_r[od], pl[kc], vf[0][j0], vf[0][j1]);
                    mma_(o_i[od], ph[kc], vf[2][j0], vf[2][j1]);
                    mma_(o_i[od], ph[kc], vf[3][j0], vf[3][j1]);
                    mma_(o_i[od], pl[kc], vf[2][j0], vf[2][j1]);
                }
            }
        __syncthreads();
    }

    // ---- normalize + write (b, tok, h*64+d) bf16 hi/lo ----
    ls0 += __shfl_xor_sync(0xffffffffu, ls0, 1);
    ls0 += __shfl_xor_sync(0xffffffffu, ls0, 2);
    ls1 += __shfl_xor_sync(0xffffffffu, ls1, 1);
    ls1 += __shfl_xor_sync(0xffffffffu, ls1, 2);
    float inv0 = 1.0f / ls0, inv1 = 1.0f / ls1;

    const int g = lane >> 2, t2 = (lane & 3) * 2;
    const int b = bh >> 3, h = bh & 7;
    const int r0 = q0 + wid * 16 + g;
#pragma unroll
    for (int od = 0; od < 8; od++) {
        int col = h * 64 + od * 8 + t2;
        size_t a0 = ((size_t)(b * NTOK + r0)) * 512 + col;
        size_t a1 = a0 + (size_t)8 * 512;
        u32 rh, rl, ih, il;
        split2(o_r[od][0] * inv0, o_r[od][1] * inv0, rh, rl);
        split2(o_i[od][0] * inv0, o_i[od][1] * inv0, ih, il);
        *(u32*)(aorh + a0) = rh; *(u32*)(aorl + a0) = rl;
        *(u32*)(aoih + a0) = ih; *(u32*)(aoil + a0) = il;
        split2(o_r[od][2] * inv1, o_r[od][3] * inv1, rh, rl);
        split2(o_i[od][2] * inv1, o_i[od][3] * inv1, ih, il);
        *(u32*)(aorh + a1) = rh; *(u32*)(aorl + a1) = rl;
        *(u32*)(aoih + a1) = ih; *(u32*)(aoil + a1) = il;
    }
}

// ---------------------------------------------------------------------------
extern "C" void kernel_launch(void* const* d_in, const int* in_sizes, int n_in,
                              void* d_out, int out_size)
{
    bf *inB, *wB, *qkvB, *aoB;
    cudaGetSymbolAddress((void**)&inB,  g_in);
    cudaGetSymbolAddress((void**)&wB,   g_w);
    cudaGetSymbolAddress((void**)&qkvB, g_qkv);
    cudaGetSymbolAddress((void**)&aoB,  g_ao);

    bf *in_[12], *w_[16], *qkv_[12], *ao_[4];
    for (int t = 0; t < 12; t++) in_[t]  = inB  + (size_t)t * NIN;
    for (int t = 0; t < 16; t++) w_[t]   = wB   + (size_t)t * NW;
    for (int t = 0; t < 12; t++) qkv_[t] = qkvB + (size_t)t * (16 * 2048 * 64);
    for (int t = 0; t < 4;  t++) ao_[t]  = aoB  + (size_t)t * (4096 * 512);

    cudaFuncSetAttribute(cgemm<0>, cudaFuncAttributeMaxDynamicSharedMemorySize, GEMM_SMEM);
    cudaFuncSetAttribute(cgemm<1>, cudaFuncAttributeMaxDynamicSharedMemorySize, GEMM_SMEM);
    cudaFuncSetAttribute(attn,     cudaFuncAttributeMaxDynamicSharedMemorySize, ATTN_SMEM);

    conv_in<<<dim3(NIN / 1024, 6), 256>>>(
        (const float*)d_in[0], (const float*)d_in[1], (const float*)d_in[2],
        (const float*)d_in[3], (const float*)d_in[4], (const float*)d_in[5], inB);
    conv_w<<<dim3(NW / 1024, 8), 256>>>(
        (const float*)d_in[6], (const float*)d_in[7], (const float*)d_in[8],
        (const float*)d_in[9], (const float*)d_in[10], (const float*)d_in[11],
        (const float*)d_in[12], (const float*)d_in[13], wB);

    dim3 gg(8, 32), blk(256);
    cgemm<0><<<gg, blk, GEMM_SMEM>>>(in_[0], in_[1], in_[2], in_[3],
                                     w_[0], w_[1], w_[2], w_[3],
                                     qkv_[0], qkv_[1], qkv_[2], qkv_[3], nullptr);
    cgemm<0><<<gg, blk, GEMM_SMEM>>>(in_[4], in_[5], in_[6], in_[7],
                                     w_[4], w_[5], w_[6], w_[7],
                                     qkv_[4], qkv_[5], qkv_[6], qkv_[7], nullptr);
    cgemm<0><<<gg, blk, GEMM_SMEM>>>(in_[8], in_[9], in_[10], in_[11],
                                     w_[8], w_[9], w_[10], w_[11],
                                     qkv_[8], qkv_[9], qkv_[10], qkv_[11], nullptr);

    attn<<<dim3(16, 16), blk, ATTN_SMEM>>>(
        qkv_[0], qkv_[1], qkv_[2], qkv_[3],
        qkv_[4], qkv_[5], qkv_[6], qkv_[7],
        qkv_[8], qkv_[9], qkv_[10], qkv_[11],
        ao_[0], ao_[1], ao_[2], ao_[3]);

    cgemm<1><<<gg, blk, GEMM_SMEM>>>(ao_[0], ao_[1], ao_[2], ao_[3],
                                     w_[12], w_[13], w_[14], w_[15],
                                     nullptr, nullptr, nullptr, nullptr, (float*)d_out);
}

// round 9
// speedup vs baseline: 1.0057x; 1.0057x over previous
#include <cuda_runtime.h>
#include <cuda_bf16.h>
#include <stdint.h>

// ============================================================================
// Complex MHA on tensor cores (mma.sync m16n8k16 bf16, fp32 accum).
// All fp32 operands split x = hi(bf16) + lo(bf16); products use 3 passes
// (hh + hl + lh)  ->  ~2^-17 relative product error.
// R7: cp.async double-buffered pipelines in cgemm + attn; merged conv.
// ============================================================================

typedef __nv_bfloat16  bf;
typedef __nv_bfloat162 bf2;
typedef uint32_t u32;

#define NTOK 2048
#define HH   8
#define NIN  (4096 * 512)
#define NW   (512 * 512)

// ------------------------------ scratch -------------------------------------
__device__ __align__(16) bf g_in [12][NIN];            // inputs  r/i x hi/lo
__device__ __align__(16) bf g_w  [16][NW];             // weights x hi/lo
__device__ __align__(16) bf g_qkv[12][16 * 2048 * 64]; // q,k,v (r/i x h/l)
__device__ __align__(16) bf g_ao [4][4096 * 512];      // attn out r/i x hi/lo

// ------------------------------ helpers -------------------------------------
__device__ __forceinline__ void ldsm4(u32* r, const bf* p) {
    u32 a = (u32)__cvta_generic_to_shared(p);
    asm volatile("ldmatrix.sync.aligned.m8n8.x4.shared.b16 {%0,%1,%2,%3},[%4];"
                 : "=r"(r[0]), "=r"(r[1]), "=r"(r[2]), "=r"(r[3]) : "r"(a));
}
__device__ __forceinline__ void ldsm4t(u32* r, const bf* p) {
    u32 a = (u32)__cvta_generic_to_shared(p);
    asm volatile("ldmatrix.sync.aligned.m8n8.x4.trans.shared.b16 {%0,%1,%2,%3},[%4];"
                 : "=r"(r[0]), "=r"(r[1]), "=r"(r[2]), "=r"(r[3]) : "r"(a));
}
__device__ __forceinline__ void mma_(float* c, const u32* a, u32 b0, u32 b1) {
    asm volatile(
        "mma.sync.aligned.m16n8k16.row.col.f32.bf16.bf16.f32 "
        "{%0,%1,%2,%3},{%4,%5,%6,%7},{%8,%9},{%0,%1,%2,%3};"
        : "+f"(c[0]), "+f"(c[1]), "+f"(c[2]), "+f"(c[3])
        : "r"(a[0]), "r"(a[1]), "r"(a[2]), "r"(a[3]), "r"(b0), "r"(b1));
}
__device__ __forceinline__ void cpa(bf* dst, const bf* src) {
    u32 a = (u32)__cvta_generic_to_shared(dst);
    asm volatile("cp.async.cg.shared.global [%0],[%1],16;" :: "r"(a), "l"(src));
}
#define CP_COMMIT asm volatile("cp.async.commit_group;")
#define CP_WAIT1  asm volatile("cp.async.wait_group 1;")
#define CP_WAIT0  asm volatile("cp.async.wait_group 0;")

// non-trans ldsm pointer: rows = (lane&15), col block = (lane>>4)*8
__device__ __forceinline__ const bf* aptr(const bf* b_, int r0, int c0, int st, int ln) {
    return b_ + (r0 + (ln & 15)) * st + c0 + ((ln >> 4) << 3);
}
// trans ldsm pointer (for B from row-major (k,n)): k = (ln&7)+((ln>>3)&1)*8
__device__ __forceinline__ const bf* tptr(const bf* b_, int r0, int c0, int st, int ln) {
    return b_ + (r0 + (ln & 7) + ((ln >> 3) & 1) * 8) * st + c0 + ((ln >> 4) & 1) * 8;
}
__device__ __forceinline__ void split2(float x0, float x1, u32& hi, u32& lo) {
    bf h0 = __float2bfloat16(x0), h1 = __float2bfloat16(x1);
    bf l0 = __float2bfloat16(x0 - __bfloat162float(h0));
    bf l1 = __float2bfloat16(x1 - __bfloat162float(h1));
    bf2 h; h.x = h0; h.y = h1; bf2 l; l.x = l0; l.y = l1;
    hi = *(u32*)&h; lo = *(u32*)&l;
}

// ------------------- fp32 -> bf16 hi/lo split (merged) ----------------------
__global__ void conv_in(const float* s0, const float* s1, const float* s2,
                        const float* s3, const float* s4, const float* s5,
                        bf* inB) {
    const int t = blockIdx.y;
    const float* s;
    switch (t) {
        case 0: s = s0; break; case 1: s = s1; break; case 2: s = s2; break;
        case 3: s = s3; break; case 4: s = s4; break; default: s = s5; break;
    }
    bf* hi = inB + (size_t)(2 * t) * NIN;
    bf* lo = hi + NIN;
    int i = (blockIdx.x * 256 + threadIdx.x) * 4;
    float4 v = *(const float4*)(s + i);
    u32 h0, l0, h1, l1;
    split2(v.x, v.y, h0, l0);
    split2(v.z, v.w, h1, l1);
    *(u32*)(hi + i) = h0; *(u32*)(hi + i + 2) = h1;
    *(u32*)(lo + i) = l0; *(u32*)(lo + i + 2) = l1;
}

__global__ void conv_w(const float* s0, const float* s1, const float* s2,
                       const float* s3, const float* s4, const float* s5,
                       const float* s6, const float* s7, bf* wB) {
    const int t = blockIdx.y;
    const float* s;
    switch (t) {
        case 0: s = s0; break; case 1: s = s1; break; case 2: s = s2; break;
        case 3: s = s3; break; case 4: s = s4; break; case 5: s = s5; break;
        case 6: s = s6; break; default: s = s7; break;
    }
    const float sc = (t < 2) ? 0.125f : 1.0f;   // fold 1/sqrt(64) into wq
    bf* hi = wB + (size_t)(2 * t) * NW;
    bf* lo = hi + NW;
    int i = (blockIdx.x * 256 + threadIdx.x) * 4;
    float4 v = *(const float4*)(s + i);
    v.x *= sc; v.y *= sc; v.z *= sc; v.w *= sc;
    u32 h0, l0, h1, l1;
    split2(v.x, v.y, h0, l0);
    split2(v.z, v.w, h1, l1);
    *(u32*)(hi + i) = h0; *(u32*)(hi + i + 2) = h1;
    *(u32*)(lo + i) = l0; *(u32*)(lo + i + 2) = l1;
}

// ---------------------------------------------------------------------------
// Complex NT GEMM (M=4096, N=512, K=512), hi/lo 3-pass bf16 mma.
// Block tile 128x64 (8 warps 4x2, warp 32x32), cp.async 2-stage pipeline.
// ---------------------------------------------------------------------------
#define ASZ (128 * 40)
#define BSZ (64 * 40)
#define STG (4 * ASZ + 4 * BSZ)
#define GEMM_SMEM (2 * STG * 2)

template<int MODE>
__global__ void __launch_bounds__(256) cgemm(
    const bf* __restrict__ A0, const bf* __restrict__ A1,
    const bf* __restrict__ A2, const bf* __restrict__ A3,
    const bf* __restrict__ B0, const bf* __restrict__ B1,
    const bf* __restrict__ B2, const bf* __restrict__ B3,
    bf* __restrict__ C0, bf* __restrict__ C1,
    bf* __restrict__ C2, bf* __restrict__ C3, float* __restrict__ Co)
{
    extern __shared__ bf sm[];
    const int tid = threadIdx.x, lane = tid & 31, wid = tid >> 5;
    const int wm = wid >> 1, wn = wid & 1;
    const int mBase = blockIdx.y * 128, nBase = blockIdx.x * 64;

    const bf* Ap[4] = {A0, A1, A2, A3};
    const bf* Bp[4] = {B0, B1, B2, B3};

    float cre[2][4][4], cim[2][4][4];
#pragma unroll
    for (int a = 0; a < 2; a++)
#pragma unroll
        for (int b = 0; b < 4; b++)
#pragma unroll
            for (int c = 0; c < 4; c++) { cre[a][b][c] = 0.f; cim[a][b][c] = 0.f; }

    // stage issue: A 4x[128x32], B 4x[64x32] via cp.async
    auto issue = [&](int kc, int d) {
        bf* sA = sm + d * STG;
        bf* sB = sA + 4 * ASZ;
#pragma unroll
        for (int t = 0; t < 4; t++) {
#pragma unroll
            for (int i = 0; i < 2; i++) {
                int idx = i * 256 + tid, row = idx >> 2, col = (idx & 3) * 8;
                cpa(sA + t * ASZ + row * 40 + col,
                    Ap[t] + (size_t)(mBase + row) * 512 + kc * 32 + col);
            }
            int row = tid >> 2, col = (tid & 3) * 8;
            cpa(sB + t * BSZ + row * 40 + col,
                Bp[t] + (size_t)(nBase + row) * 512 + kc * 32 + col);
        }
    };

    issue(0, 0); CP_COMMIT;

    for (int kc = 0; kc < 16; kc++) {
        if (kc < 15) { issue(kc + 1, (kc + 1) & 1); CP_COMMIT; CP_WAIT1; }
        else         { CP_WAIT0; }
        __syncthreads();

        bf* sA = sm + (kc & 1) * STG;
        bf* sB = sA + 4 * ASZ;

#pragma unroll
        for (int ks = 0; ks < 2; ks++) {
            u32 af[4][2][4];
#pragma unroll
            for (int t = 0; t < 4; t++)
#pragma unroll
                for (int mt = 0; mt < 2; mt++)
                    ldsm4(af[t][mt], aptr(sA + t * ASZ, wm * 32 + mt * 16, ks * 16, 40, lane));
            u32 bg[4][8];
#pragma unroll
            for (int t = 0; t < 4; t++) {
                ldsm4(bg[t],     aptr(sB + t * BSZ, wn * 32,      ks * 16, 40, lane));
                ldsm4(bg[t] + 4, aptr(sB + t * BSZ, wn * 32 + 16, ks * 16, 40, lane));
            }
#pragma unroll
            for (int mt = 0; mt < 2; mt++) {
                u32 n2[4], n3[4];   // negated Ai hi/lo
#pragma unroll
                for (int r = 0; r < 4; r++) {
                    n2[r] = af[2][mt][r] ^ 0x80008000u;
                    n3[r] = af[3][mt][r] ^ 0x80008000u;
                }
#pragma unroll
                for (int nt = 0; nt < 4; nt++) {
                    int i0 = (nt >> 1) * 4 + (nt & 1), i1 = i0 + 2;
                    float* cr = cre[mt][nt]; float* ci = cim[mt][nt];
                    mma_(cr, af[0][mt], bg[0][i0], bg[0][i1]);
                    mma_(cr, af[0][mt], bg[1][i0], bg[1][i1]);
                    mma_(cr, af[1][mt], bg[0][i0], bg[0][i1]);
                    mma_(cr, n2,        bg[2][i0], bg[2][i1]);
                    mma_(cr, n2,        bg[3][i0], bg[3][i1]);
                    mma_(cr, n3,        bg[2][i0], bg[2][i1]);
                    mma_(ci, af[0][mt], bg[2][i0], bg[2][i1]);
                    mma_(ci, af[0][mt], bg[3][i0], bg[3][i1]);
                    mma_(ci, af[1][mt], bg[2][i0], bg[2][i1]);
                    mma_(ci, af[2][mt], bg[0][i0], bg[0][i1]);
                    mma_(ci, af[2][mt], bg[1][i0], bg[1][i1]);
                    mma_(ci, af[3][mt], bg[0][i0], bg[0][i1]);
                }
            }
        }
        __syncthreads();
    }

    const int g = lane >> 2, t2 = (lane & 3) * 2;
#pragma unroll
    for (int mt = 0; mt < 2; mt++)
#pragma unroll
        for (int nt = 0; nt < 4; nt++) {
            int c0 = wn * 32 + nt * 8 + t2;
#pragma unroll
            for (int hf = 0; hf < 2; hf++) {
                int m = mBase + wm * 32 + mt * 16 + g + hf * 8;
                float yr0 = cre[mt][nt][hf * 2], yr1 = cre[mt][nt][hf * 2 + 1];
                float yi0 = cim[mt][nt][hf * 2], yi1 = cim[mt][nt][hf * 2 + 1];
                if (MODE == 0) {
                    int b = m >> 11, ntok = m & 2047, h = blockIdx.x;
                    size_t base = ((size_t)((b * HH + h) * NTOK + ntok)) * 64 + c0;
                    u32 rh, rl, ih, il;
                    split2(yr0, yr1, rh, rl);
                    split2(yi0, yi1, ih, il);
                    *(u32*)(C0 + base) = rh; *(u32*)(C1 + base) = rl;
                    *(u32*)(C2 + base) = ih; *(u32*)(C3 + base) = il;
                } else {
                    size_t base = ((size_t)m * 512 + nBase + c0) * 2;
                    *(float4*)(Co + base) = make_float4(yr0, yi0, yr1, yi1);
                }
            }
        }
}

// ---------------------------------------------------------------------------
// Fused complex attention, cp.async 2-stage K/V pipeline.
// Grid (16 q-blocks, 16 bh). 8 warps; warp = 16 q rows x full 64-k tile.
// ---------------------------------------------------------------------------
#define QS (128 * 72)
#define KS (64 * 72)
#define KVSTG (8 * KS)
#define ATTN_SMEM ((4 * QS + 2 * KVSTG) * 2)

__global__ void __launch_bounds__(256) attn(
    const bf* __restrict__ q0p, const bf* __restrict__ q1p,
    const bf* __restrict__ q2p, const bf* __restrict__ q3p,
    const bf* __restrict__ k0p, const bf* __restrict__ k1p,
    const bf* __restrict__ k2p, const bf* __restrict__ k3p,
    const bf* __restrict__ v0p, const bf* __restrict__ v1p,
    const bf* __restrict__ v2p, const bf* __restrict__ v3p,
    bf* __restrict__ aorh, bf* __restrict__ aorl,
    bf* __restrict__ aoih, bf* __restrict__ aoil)
{
    extern __shared__ bf sm[];
    bf* sQ = sm;

    const int tid = threadIdx.x, lane = tid & 31, wid = tid >> 5;
    const int bh = blockIdx.y, q0 = blockIdx.x * 128;
    const bf* qp[4] = {q0p, q1p, q2p, q3p};
    const bf* kp[4] = {k0p, k1p, k2p, k3p};
    const bf* vp[4] = {v0p, v1p, v2p, v3p};

    auto issue_kv = [&](int kt, int d) {
        bf* sK = sm + 4 * QS + d * KVSTG;
        bf* sV = sK + 4 * KS;
#pragma unroll
        for (int t = 0; t < 4; t++)
#pragma unroll
            for (int i = 0; i < 2; i++) {
                int idx = i * 256 + tid, row = idx >> 3, col = (idx & 7) * 8;
                size_t go = ((size_t)(bh * NTOK + kt * 64 + row)) * 64 + col;
                cpa(sK + t * KS + row * 72 + col, kp[t] + go);
                cpa(sV + t * KS + row * 72 + col, vp[t] + go);
            }
    };

    issue_kv(0, 0); CP_COMMIT;

    // load Q tile once (plain stores; visible after first barrier)
#pragma unroll
    for (int t = 0; t < 4; t++)
#pragma unroll
        for (int i = 0; i < 4; i++) {
            int idx = i * 256 + tid, row = idx >> 3, col = (idx & 7) * 8;
            *(float4*)(sQ + t * QS + row * 72 + col) =
                *(const float4*)(qp[t] + ((size_t)(bh * NTOK + q0 + row)) * 64 + col);
        }

    float o_r[8][4], o_i[8][4];
#pragma unroll
    for (int a = 0; a < 8; a++)
#pragma unroll
        for (int b = 0; b < 4; b++) { o_r[a][b] = 0.f; o_i[a][b] = 0.f; }
    float ls0 = 0.f, ls1 = 0.f;

    for (int kt = 0; kt < 32; kt++) {
        if (kt < 31) { issue_kv(kt + 1, (kt + 1) & 1); CP_COMMIT; CP_WAIT1; }
        else         { CP_WAIT0; }
        __syncthreads();

        bf* sK = sm + 4 * QS + (kt & 1) * KVSTG;
        bf* sV = sK + 4 * KS;

        // ---- scores: S = Q conj(K)^T (hi/lo 3-pass) ----
        float sre[8][4], sim[8][4];
#pragma unroll
        for (int a = 0; a < 8; a++)
#pragma unroll
            for (int b = 0; b < 4; b++) { sre[a][b] = 0.f; sim[a][b] = 0.f; }

#pragma unroll
        for (int dc = 0; dc < 4; dc++) {
            u32 qf[4][4];
#pragma unroll
            for (int t = 0; t < 4; t++)
                ldsm4(qf[t], aptr(sQ + t * QS, wid * 16, dc * 16, 72, lane));
            u32 n0[4], n1[4];
#pragma unroll
            for (int r = 0; r < 4; r++) {
                n0[r] = qf[0][r] ^ 0x80008000u;
                n1[r] = qf[1][r] ^ 0x80008000u;
            }
#pragma unroll
            for (int nh = 0; nh < 2; nh++) {
                u32 kf[4][8];
#pragma unroll
                for (int t = 0; t < 4; t++) {
                    ldsm4(kf[t],     aptr(sK + t * KS, nh * 32,      dc * 16, 72, lane));
                    ldsm4(kf[t] + 4, aptr(sK + t * KS, nh * 32 + 16, dc * 16, 72, lane));
                }
#pragma unroll
                for (int n4 = 0; n4 < 4; n4++) {
                    int nt = nh * 4 + n4;
                    int i0 = (n4 >> 1) * 4 + (n4 & 1), i1 = i0 + 2;
                    float* cr = sre[nt]; float* ci = sim[nt];
                    mma_(cr, qf[0], kf[0][i0], kf[0][i1]);
                    mma_(cr, qf[0], kf[1][i0], kf[1][i1]);
                    mma_(cr, qf[1], kf[0][i0], kf[0][i1]);
                    mma_(cr, qf[2], kf[2][i0], kf[2][i1]);
                    mma_(cr, qf[2], kf[3][i0], kf[3][i1]);
                    mma_(cr, qf[3], kf[2][i0], kf[2][i1]);
                    mma_(ci, qf[2], kf[0][i0], kf[0][i1]);
                    mma_(ci, qf[2], kf[1][i0], kf[1][i1]);
                    mma_(ci, qf[3], kf[0][i0], kf[0][i1]);
                    mma_(ci, n0,    kf[2][i0], kf[2][i1]);
                    mma_(ci, n0,    kf[3][i0], kf[3][i1]);
                    mma_(ci, n1,    kf[2][i0], kf[2][i1]);
                }
            }
        }

        // ---- p = exp(|s|), register repack S-accum -> P A-frags ----
        u32 ph[4][4], pl[4][4];
#pragma unroll
        for (int kc = 0; kc < 4; kc++) {
            float pv[2][4];
#pragma unroll
            for (int h2 = 0; h2 < 2; h2++) {
                int nt = kc * 2 + h2;
#pragma unroll
                for (int e = 0; e < 4; e++) {
                    float u = sre[nt][e] * sre[nt][e] + sim[nt][e] * sim[nt][e];
                    pv[h2][e] = __expf(__fsqrt_rn(u));
                }
            }
            ls0 += pv[0][0] + pv[0][1] + pv[1][0] + pv[1][1];
            ls1 += pv[0][2] + pv[0][3] + pv[1][2] + pv[1][3];
            split2(pv[0][0], pv[0][1], ph[kc][0], pl[kc][0]);
            split2(pv[0][2], pv[0][3], ph[kc][1], pl[kc][1]);
            split2(pv[1][0], pv[1][1], ph[kc][2], pl[kc][2]);
            split2(pv[1][2], pv[1][3], ph[kc][3], pl[kc][3]);
        }

        // ---- O += P V (hi/lo 3-pass), V via trans ldmatrix ----
#pragma unroll
        for (int kc = 0; kc < 4; kc++)
#pragma unroll
            for (int dh = 0; dh < 2; dh++) {
                u32 vf[4][8];
#pragma unroll
                for (int t = 0; t < 4; t++) {
                    ldsm4t(vf[t],     tptr(sV + t * KS, kc * 16, dh * 32,      72, lane));
                    ldsm4t(vf[t] + 4, tptr(sV + t * KS, kc * 16, dh * 32 + 16, 72, lane));
                }
#pragma unroll
                for (int dt = 0; dt < 4; dt++) {
                    int od = dh * 4 + dt, j0 = dt * 2, j1 = dt * 2 + 1;
                    mma_(o_r[od], ph[kc], vf[0][j0], vf[0][j1]);
                    mma_(o_r[od], ph[kc], vf[1][j0], vf[1][j1]);
                    mma_(o_r[od], pl[kc], vf[0][j0], vf[0][j1]);
                    mma_(o_i[od], ph[kc], vf[2][j0], vf[2][j1]);
                    mma_(o_i[od], ph[kc], vf[3][j0], vf[3][j1]);
                    mma_(o_i[od], pl[kc], vf[2][j0], vf[2][j1]);
                }
            }
        __syncthreads();
    }

    // ---- normalize + write (b, tok, h*64+d) bf16 hi/lo ----
    ls0 += __shfl_xor_sync(0xffffffffu, ls0, 1);
    ls0 += __shfl_xor_sync(0xffffffffu, ls0, 2);
    ls1 += __shfl_xor_sync(0xffffffffu, ls1, 1);
    ls1 += __shfl_xor_sync(0xffffffffu, ls1, 2);
    float inv0 = 1.0f / ls0, inv1 = 1.0f / ls1;

    const int g = lane >> 2, t2 = (lane & 3) * 2;
    const int b = bh >> 3, h = bh & 7;
    const int r0 = q0 + wid * 16 + g;
#pragma unroll
    for (int od = 0; od < 8; od++) {
        int col = h * 64 + od * 8 + t2;
        size_t a0 = ((size_t)(b * NTOK + r0)) * 512 + col;
        size_t a1 = a0 + (size_t)8 * 512;
        u32 rh, rl, ih, il;
        split2(o_r[od][0] * inv0, o_r[od][1] * inv0, rh, rl);
        split2(o_i[od][0] * inv0, o_i[od][1] * inv0, ih, il);
        *(u32*)(aorh + a0) = rh; *(u32*)(aorl + a0) = rl;
        *(u32*)(aoih + a0) = ih; *(u32*)(aoil + a0) = il;
        split2(o_r[od][2] * inv1, o_r[od][3] * inv1, rh, rl);
        split2(o_i[od][2] * inv1, o_i[od][3] * inv1, ih, il);
        *(u32*)(aorh + a1) = rh; *(u32*)(aorl + a1) = rl;
        *(u32*)(aoih + a1) = ih; *(u32*)(aoil + a1) = il;
    }
}

// ---------------------------------------------------------------------------
extern "C" void kernel_launch(void* const* d_in, const int* in_sizes, int n_in,
                              void* d_out, int out_size)
{
    bf *inB, *wB, *qkvB, *aoB;
    cudaGetSymbolAddress((void**)&inB,  g_in);
    cudaGetSymbolAddress((void**)&wB,   g_w);
    cudaGetSymbolAddress((void**)&qkvB, g_qkv);
    cudaGetSymbolAddress((void**)&aoB,  g_ao);

    bf *in_[12], *w_[16], *qkv_[12], *ao_[4];
    for (int t = 0; t < 12; t++) in_[t]  = inB  + (size_t)t * NIN;
    for (int t = 0; t < 16; t++) w_[t]   = wB   + (size_t)t * NW;
    for (int t = 0; t < 12; t++) qkv_[t] = qkvB + (size_t)t * (16 * 2048 * 64);
    for (int t = 0; t < 4;  t++) ao_[t]  = aoB  + (size_t)t * (4096 * 512);

    cudaFuncSetAttribute(cgemm<0>, cudaFuncAttributeMaxDynamicSharedMemorySize, GEMM_SMEM);
    cudaFuncSetAttribute(cgemm<1>, cudaFuncAttributeMaxDynamicSharedMemorySize, GEMM_SMEM);
    cudaFuncSetAttribute(attn,     cudaFuncAttributeMaxDynamicSharedMemorySize, ATTN_SMEM);

    conv_in<<<dim3(NIN / 1024, 6), 256>>>(
        (const float*)d_in[0], (const float*)d_in[1], (const float*)d_in[2],
        (const float*)d_in[3], (const float*)d_in[4], (const float*)d_in[5], inB);
    conv_w<<<dim3(NW / 1024, 8), 256>>>(
        (const float*)d_in[6], (const float*)d_in[7], (const float*)d_in[8],
        (const float*)d_in[9], (const float*)d_in[10], (const float*)d_in[11],
        (const float*)d_in[12], (const float*)d_in[13], wB);

    dim3 gg(8, 32), blk(256);
    cgemm<0><<<gg, blk, GEMM_SMEM>>>(in_[0], in_[1], in_[2], in_[3],
                                     w_[0], w_[1], w_[2], w_[3],
                                     qkv_[0], qkv_[1], qkv_[2], qkv_[3], nullptr);
    cgemm<0><<<gg, blk, GEMM_SMEM>>>(in_[4], in_[5], in_[6], in_[7],
                                     w_[4], w_[5], w_[6], w_[7],
                                     qkv_[4], qkv_[5], qkv_[6], qkv_[7], nullptr);
    cgemm<0><<<gg, blk, GEMM_SMEM>>>(in_[8], in_[9], in_[10], in_[11],
                                     w_[8], w_[9], w_[10], w_[11],
                                     qkv_[8], qkv_[9], qkv_[10], qkv_[11], nullptr);

    attn<<<dim3(16, 16), blk, ATTN_SMEM>>>(
        qkv_[0], qkv_[1], qkv_[2], qkv_[3],
        qkv_[4], qkv_[5], qkv_[6], qkv_[7],
        qkv_[8], qkv_[9], qkv_[10], qkv_[11],
        ao_[0], ao_[1], ao_[2], ao_[3]);

    cgemm<1><<<gg, blk, GEMM_SMEM>>>(ao_[0], ao_[1], ao_[2], ao_[3],
                                     w_[12], w_[13], w_[14], w_[15],
                                     nullptr, nullptr, nullptr, nullptr, (float*)d_out);
}